// round 11
// baseline (speedup 1.0000x reference)
#include <cuda_runtime.h>

// MeshFit update_points_feat: per-class exact kNN (K=3) + softmax-weighted
// feature gather. C=4, N=4096, M=4096, D=32. Output (1, C*M, D) float32.
//
// R11: 16x16 grid, 8 lanes/query (4 groups/warp), queries cell-sorted, and
// the ring walk uses ONE WARP-SHARED CENTER (group 0's cell) -> all ring/cell
// control flow is warp-uniform and point LDS is 4-way broadcast across
// groups. (dist, idx) packed into u64 keys: float-bit order == numeric order
// for d >= 0, so one u64 compare == exact lexicographic (d, idx) ==
// jax.lax.top_k tie-breaking. Per-group stop bound vs own query's distance
// to the covered square (<=0 => cannot stop; domain wall => +inf); finished
// groups keep scanning harmlessly (post-done points are strictly farther
// than d2, margin-protected). Warp breaks on __all_sync(done).

#define CC    4
#define NV    4096
#define MV    4096
#define DF    32
#define GW    16
#define NCELL (GW * GW)
#define CELLW (1.0f / GW)
#define QL    8
#define TBQ   512
#define QPB   (TBQ / QL)            // 64 queries per block
#define NBLKQ ((CC * MV) / QPB)     // 256 blocks

typedef unsigned long long u64;

__device__ float4 g_binned[CC][NV];           // (x, y, z, idx) in bin order
__device__ int    g_cellStart[CC][NCELL + 1];
__device__ int    g_qorder[CC][MV];           // query ids sorted by cell

__device__ __forceinline__ int clampg(int v) {
    return v < 0 ? 0 : (v > GW - 1 ? GW - 1 : v);
}

// Branchless sorted-top-3 insert on packed (dist,idx) keys; u64 '<' is the
// exact lexicographic (d asc, idx asc) order for non-negative distances.
__device__ __forceinline__ void kins(u64 k, u64& k0, u64& k1, u64& k2)
{
    const bool c0 = k < k0;
    const bool c1 = k < k1;
    const bool c2 = k < k2;
    k2 = c1 ? k1 : (c2 ? k : k2);
    k1 = c0 ? k0 : (c1 ? k : k1);
    k0 = c0 ? k  : k0;
}

__device__ __forceinline__ u64 mkkey(float t, unsigned idx) {
    return ((u64)__float_as_uint(t) << 32) | (u64)idx;
}
__device__ __forceinline__ float key_d(u64 k) {
    return __uint_as_float((unsigned)(k >> 32));
}
__device__ __forceinline__ int key_i(u64 k) {
    return (int)(unsigned)k;
}

// ---- K1: bin points + sort queries (8 blocks, smem-only counters) --------
__global__ void __launch_bounds__(1024, 1)
prep_kernel(const float* __restrict__ verts,
            const float* __restrict__ nverts)
{
    __shared__ int cnt[NCELL];
    __shared__ int sc[NCELL];
    __shared__ int offs[NCELL];
    const int b   = blockIdx.x;
    const int tid = threadIdx.x;
    const bool role = (b >= CC);               // 0: points, 1: queries
    const int  c    = role ? b - CC : b;
    const int  len  = role ? MV : NV;
    const float* src = role ? (nverts + (size_t)c * MV * 3)
                            : (verts + (size_t)c * NV * 3);

    if (tid < NCELL) cnt[tid] = 0;
    __syncthreads();

    for (int n = tid; n < len; n += 1024) {
        const int cx = clampg((int)(src[3 * n + 0] * GW));
        const int cy = clampg((int)(src[3 * n + 1] * GW));
        atomicAdd(&cnt[cy * GW + cx], 1);
    }
    __syncthreads();

    if (tid < NCELL) sc[tid] = cnt[tid];
    __syncthreads();
#pragma unroll
    for (int st = 1; st < NCELL; st <<= 1) {
        int add = 0;
        if (tid < NCELL && tid >= st) add = sc[tid - st];
        __syncthreads();
        if (tid < NCELL) sc[tid] += add;
        __syncthreads();
    }
    if (tid < NCELL) {
        offs[tid] = sc[tid] - cnt[tid];        // exclusive prefix
        if (!role) g_cellStart[c][tid] = offs[tid];
    }
    if (!role && tid == 0) g_cellStart[c][NCELL] = NV;
    __syncthreads();

    for (int n = tid; n < len; n += 1024) {
        const float x = src[3 * n + 0], y = src[3 * n + 1];
        const int cell = clampg((int)(y * GW)) * GW + clampg((int)(x * GW));
        const int slot = atomicAdd(&offs[cell], 1);
        if (role) g_qorder[c][slot] = n;
        else      g_binned[c][slot] = make_float4(x, y, src[3 * n + 2],
                                                  __int_as_float(n));
    }
}

// ---- K2: shared-center ring search, 8 lanes/query ------------------------
__global__ void __launch_bounds__(TBQ, 2)
query_kernel(const float* __restrict__ feat,
             const float* __restrict__ nverts,
             float* __restrict__ out)
{
    extern __shared__ char smem[];
    float4* spts   = (float4*)smem;                      // 64 KB
    int*    sStart = (int*)(smem + NV * sizeof(float4)); // 257 ints

    const int tid  = threadIdx.x;
    const int lane = tid & 31;
    const int lq   = tid & (QL - 1);
    const int c    = blockIdx.x >> 6;          // 64 blocks per class
    const int slot = (blockIdx.x & 63) * QPB + (tid >> 3);

    // Stage this class's binned points + cell table.
    for (int i = tid; i < NV; i += TBQ) spts[i] = g_binned[c][i];
    for (int i = tid; i < NCELL + 1; i += TBQ) sStart[i] = g_cellStart[c][i];
    __syncthreads();

    const int m = g_qorder[c][slot];
    const float* q = nverts + ((size_t)c * MV + m) * 3;
    const float qx = q[0], qy = q[1], qz = q[2];

    // Warp-shared ring center: the cell of the warp's first query.
    const int cx = clampg((int)(qx * GW));
    const int cy = clampg((int)(qy * GW));
    const int wcx = __shfl_sync(0xffffffffu, cx, 0);
    const int wcy = __shfl_sync(0xffffffffu, cy, 0);

    u64 k0 = 0x7F800000FFFFFFFFull;   // (+inf, idx_max)
    u64 k1 = 0x7F800000FFFFFFFFull;
    u64 k2 = 0x7F800000FFFFFFFFull;

    bool done = false;
#pragma unroll 1
    for (int r = 0; r < GW; ++r) {
        const int y0 = wcy - r < 0 ? 0 : wcy - r;
        const int y1 = wcy + r > GW - 1 ? GW - 1 : wcy + r;
        const int x0 = wcx - r < 0 ? 0 : wcx - r;
        const int x1 = wcx + r > GW - 1 ? GW - 1 : wcx + r;
#pragma unroll 1
        for (int Y = y0; Y <= y1; ++Y) {
            const bool edge_y = (Y == wcy - r) || (Y == wcy + r);
#pragma unroll 1
            for (int X = x0; X <= x1; ++X) {
                if (!edge_y && X != wcx - r && X != wcx + r) continue;
                const int cell = Y * GW + X;                 // warp-uniform
                const int s = sStart[cell], e = sStart[cell + 1];
                for (int p = s + lq; p < e; p += QL) {       // 4-way bcast LDS
                    const float4 pt = spts[p];
                    const float dx = qx - pt.x;
                    const float dy = qy - pt.y;
                    const float dz = qz - pt.z;
                    const float t = fmaf(dz, dz, fmaf(dy, dy, dx * dx));
                    kins(mkkey(t, (unsigned)__float_as_int(pt.w)),
                         k0, k1, k2);
                }
            }
        }
        // Per-group stop bound. B = min over the 8 lanes of local d2
        // (>= true d2). dmin = own query's distance to the covered-square
        // boundary; <= 0 (query outside / at wall of square) => cannot stop.
        float B = key_d(k2);
#pragma unroll
        for (int off = 1; off < QL; off <<= 1)
            B = fminf(B, __shfl_xor_sync(0xffffffffu, B, off));
        const float sL = (wcx - r <= 0)      ? 1e30f : qx - (wcx - r) * CELLW;
        const float sR = (wcx + r >= GW - 1) ? 1e30f : (wcx + r + 1) * CELLW - qx;
        const float sB = (wcy - r <= 0)      ? 1e30f : qy - (wcy - r) * CELLW;
        const float sT = (wcy + r >= GW - 1) ? 1e30f : (wcy + r + 1) * CELLW - qy;
        const float dmin = fminf(fminf(sL, sR), fminf(sB, sT));
        done = done || ((dmin > 0.0f) && (B * 1.00001f < dmin * dmin));
        if (__all_sync(0xffffffffu, done)) break;
    }

    // Butterfly merge across the 8 lanes of this group (exact lex order).
#pragma unroll
    for (int off = 1; off < QL; off <<= 1) {
        const u64 p0 = __shfl_xor_sync(0xffffffffu, k0, off);
        const u64 p1 = __shfl_xor_sync(0xffffffffu, k1, off);
        const u64 p2 = __shfl_xor_sync(0xffffffffu, k2, off);
        kins(p0, k0, k1, k2);
        kins(p1, k0, k1, k2);
        kins(p2, k0, k1, k2);
    }

    // Local -> global column index (low-word add; no carry possible), then
    // exact merge of the constant-1.0 off-block fillers.
    const u64 base = (u64)(c * NV);
    k0 += base; k1 += base; k2 += base;
    const unsigned fbase = (c == 0) ? NV : 0;
#pragma unroll
    for (int k = 0; k < 3; ++k)
        kins(((u64)0x3F800000u << 32) | (u64)(fbase + k), k0, k1, k2);

    const float d0 = key_d(k0), d1 = key_d(k1), d2 = key_d(k2);
    const int   g0 = key_i(k0), g1 = key_i(k1), g2 = key_i(k2);

    // softmax(-d), max-subtracted (d0 smallest).
    const float e1 = expf(d0 - d1);
    const float e2 = expf(d0 - d2);
    const float inv = 1.0f / (1.0f + e1 + e2);
    const float w0 = inv, w1 = e1 * inv, w2 = e2 * inv;

    // All 8 lanes hold the identical top-3; each writes one float4 chunk.
    const float4 a  = __ldg(&((const float4*)(feat + (size_t)g0 * DF))[lq]);
    const float4 b  = __ldg(&((const float4*)(feat + (size_t)g1 * DF))[lq]);
    const float4 cv = __ldg(&((const float4*)(feat + (size_t)g2 * DF))[lq]);
    float4 rr;
    rr.x = w0 * a.x + w1 * b.x + w2 * cv.x;
    rr.y = w0 * a.y + w1 * b.y + w2 * cv.y;
    rr.z = w0 * a.z + w1 * b.z + w2 * cv.z;
    rr.w = w0 * a.w + w1 * b.w + w2 * cv.w;
    ((float4*)(out + ((size_t)c * MV + m) * DF))[lq] = rr;
    (void)lane;
}

extern "C" void kernel_launch(void* const* d_in, const int* in_sizes, int n_in,
                              void* d_out, int out_size)
{
    const float* feat   = (const float*)d_in[0];  // (1, C*N, D)
    const float* verts  = (const float*)d_in[1];  // (C, N, 3)
    const float* nverts = (const float*)d_in[2];  // (C, M, 3)
    float* out = (float*)d_out;                   // (1, C*M, D)

    prep_kernel<<<2 * CC, 1024>>>(verts, nverts);

    const int smem = NV * sizeof(float4) + (NCELL + 1) * sizeof(int);
    cudaFuncSetAttribute(query_kernel,
                         cudaFuncAttributeMaxDynamicSharedMemorySize, smem);
    query_kernel<<<NBLKQ, TBQ, smem>>>(feat, nverts, out);
}

// round 12
// speedup vs baseline: 4.6349x; 4.6349x over previous
#include <cuda_runtime.h>

// MeshFit update_points_feat: per-class exact kNN (K=3) + softmax-weighted
// feature gather. C=4, N=4096, M=4096, D=32. Output (1, C*M, D) float32.
//
// R12 = R8 structure (16x16 grid, 8 lanes/query, per-group ring centers and
// stop bounds) + u64 packed (dist,idx) keys (single compare = exact
// lexicographic (d, idx) = jax.lax.top_k order) + ROW-RANGE scanning (ring
// rows are contiguous slot ranges in the row-major cell layout -> fewer,
// longer inner loops) + parallel-scan prep. Stop bound per group: B = min
// over 8 lanes of local d2 (>= true d2); skip region strictly farther
// (1e-5 margin) => lossless.

#define CC    4
#define NV    4096
#define MV    4096
#define DF    32
#define GW    16
#define NCELL (GW * GW)
#define CELLW (1.0f / GW)
#define QL    8
#define TB    1024
#define QPB   (TB / QL)            // 128 queries per block
#define NBLK  ((CC * MV) / QPB)    // 128 blocks

typedef unsigned long long u64;

__device__ float4 g_binned[CC][NV];           // (x, y, z, idx) in bin order
__device__ int    g_cellStart[CC][NCELL + 1];
__device__ int    g_qorder[CC][MV];           // query ids sorted by cell

__device__ __forceinline__ int clampg(int v) {
    return v < 0 ? 0 : (v > GW - 1 ? GW - 1 : v);
}

// Branchless sorted-top-3 insert on packed (dist,idx) keys; u64 '<' ==
// exact lexicographic (d asc, idx asc) for non-negative distances.
__device__ __forceinline__ void kins(u64 k, u64& k0, u64& k1, u64& k2)
{
    const bool c0 = k < k0;
    const bool c1 = k < k1;
    const bool c2 = k < k2;
    k2 = c1 ? k1 : (c2 ? k : k2);
    k1 = c0 ? k0 : (c1 ? k : k1);
    k0 = c0 ? k  : k0;
}

__device__ __forceinline__ float key_d(u64 k) {
    return __uint_as_float((unsigned)(k >> 32));
}
__device__ __forceinline__ int key_i(u64 k) {
    return (int)(unsigned)k;
}

// ---- K1: bin points + sort queries (8 blocks, parallel scan) -------------
__global__ void __launch_bounds__(1024, 1)
prep_kernel(const float* __restrict__ verts,
            const float* __restrict__ nverts)
{
    __shared__ int cnt[NCELL];
    __shared__ int sc[NCELL];
    __shared__ int offs[NCELL];
    const int b   = blockIdx.x;
    const int tid = threadIdx.x;
    const bool role = (b >= CC);               // 0: points, 1: queries
    const int  c    = role ? b - CC : b;
    const int  len  = role ? MV : NV;
    const float* src = role ? (nverts + (size_t)c * MV * 3)
                            : (verts + (size_t)c * NV * 3);

    if (tid < NCELL) cnt[tid] = 0;
    __syncthreads();

    for (int n = tid; n < len; n += 1024) {
        const int cx = clampg((int)(src[3 * n + 0] * GW));
        const int cy = clampg((int)(src[3 * n + 1] * GW));
        atomicAdd(&cnt[cy * GW + cx], 1);
    }
    __syncthreads();

    if (tid < NCELL) sc[tid] = cnt[tid];
    __syncthreads();
#pragma unroll
    for (int st = 1; st < NCELL; st <<= 1) {
        int add = 0;
        if (tid < NCELL && tid >= st) add = sc[tid - st];
        __syncthreads();
        if (tid < NCELL) sc[tid] += add;
        __syncthreads();
    }
    if (tid < NCELL) {
        offs[tid] = sc[tid] - cnt[tid];        // exclusive prefix
        if (!role) g_cellStart[c][tid] = offs[tid];
    }
    if (!role && tid == 0) g_cellStart[c][NCELL] = NV;
    __syncthreads();

    for (int n = tid; n < len; n += 1024) {
        const float x = src[3 * n + 0], y = src[3 * n + 1];
        const int cell = clampg((int)(y * GW)) * GW + clampg((int)(x * GW));
        const int slot = atomicAdd(&offs[cell], 1);
        if (role) g_qorder[c][slot] = n;
        else      g_binned[c][slot] = make_float4(x, y, src[3 * n + 2],
                                                  __int_as_float(n));
    }
}

// Scan a contiguous slot range [s, e) with the group's 8 lanes.
__device__ __forceinline__ void scan_range(const float4* __restrict__ spts,
                                           int s, int e, int lq,
                                           float qx, float qy, float qz,
                                           u64& k0, u64& k1, u64& k2)
{
    for (int p = s + lq; p < e; p += QL) {
        const float4 pt = spts[p];
        const float dx = qx - pt.x;
        const float dy = qy - pt.y;
        const float dz = qz - pt.z;
        const float t = fmaf(dz, dz, fmaf(dy, dy, dx * dx));
        const u64 k = ((u64)__float_as_uint(t) << 32)
                    | (u64)(unsigned)__float_as_int(pt.w);
        kins(k, k0, k1, k2);
    }
}

// ---- K2: per-group ring search with row-range scanning -------------------
__global__ void __launch_bounds__(TB, 1)
query_kernel(const float* __restrict__ feat,
             const float* __restrict__ nverts,
             float* __restrict__ out)
{
    extern __shared__ char smem[];
    float4* spts   = (float4*)smem;                      // 64 KB
    int*    sStart = (int*)(smem + NV * sizeof(float4)); // 257 ints

    const int tid = threadIdx.x;
    const int lq  = tid & (QL - 1);
    const int c    = blockIdx.x >> 5;          // 32 blocks per class
    const int slot = (blockIdx.x & 31) * QPB + (tid >> 3);

    // Stage this class's binned points + cell table.
    for (int i = tid; i < NV; i += TB) spts[i] = g_binned[c][i];
    for (int i = tid; i < NCELL + 1; i += TB) sStart[i] = g_cellStart[c][i];
    __syncthreads();

    const int m = g_qorder[c][slot];
    const float* q = nverts + ((size_t)c * MV + m) * 3;
    const float qx = q[0], qy = q[1], qz = q[2];
    const int cx = clampg((int)(qx * GW));
    const int cy = clampg((int)(qy * GW));

    u64 k0 = 0x7F800000FFFFFFFFull;   // (+inf, idx_max)
    u64 k1 = 0x7F800000FFFFFFFFull;
    u64 k2 = 0x7F800000FFFFFFFFull;

    bool done = false;
#pragma unroll 1
    for (int r = 0; r < GW; ++r) {
        if (!done) {
            const int x0 = cx - r < 0 ? 0 : cx - r;
            const int x1 = cx + r > GW - 1 ? GW - 1 : cx + r;
            if (r == 0) {
                const int cell = cy * GW + cx;
                scan_range(spts, sStart[cell], sStart[cell + 1], lq,
                           qx, qy, qz, k0, k1, k2);
            } else {
                // Top and bottom rows: contiguous ranges of 2r+1 cells.
                if (cy - r >= 0) {
                    const int cb = (cy - r) * GW;
                    scan_range(spts, sStart[cb + x0], sStart[cb + x1 + 1], lq,
                               qx, qy, qz, k0, k1, k2);
                }
                if (cy + r <= GW - 1) {
                    const int cb = (cy + r) * GW;
                    scan_range(spts, sStart[cb + x0], sStart[cb + x1 + 1], lq,
                               qx, qy, qz, k0, k1, k2);
                }
                // Middle rows: two isolated cells each.
                const int ym0 = cy - r + 1 < 0 ? 0 : cy - r + 1;
                const int ym1 = cy + r - 1 > GW - 1 ? GW - 1 : cy + r - 1;
#pragma unroll 1
                for (int Y = ym0; Y <= ym1; ++Y) {
                    const int cb = Y * GW;
                    if (cx - r >= 0)
                        scan_range(spts, sStart[cb + cx - r],
                                   sStart[cb + cx - r + 1], lq,
                                   qx, qy, qz, k0, k1, k2);
                    if (cx + r <= GW - 1)
                        scan_range(spts, sStart[cb + cx + r],
                                   sStart[cb + cx + r + 1], lq,
                                   qx, qy, qz, k0, k1, k2);
                }
            }
        }
        // Stop bound: B = min over the 8 lanes of local d2 (>= true d2).
        float B = key_d(k2);
#pragma unroll
        for (int off = 1; off < QL; off <<= 1)
            B = fminf(B, __shfl_xor_sync(0xffffffffu, B, off));
        const float sL = (cx - r <= 0)      ? 1e30f : qx - (cx - r) * CELLW;
        const float sR = (cx + r >= GW - 1) ? 1e30f : (cx + r + 1) * CELLW - qx;
        const float sB = (cy - r <= 0)      ? 1e30f : qy - (cy - r) * CELLW;
        const float sT = (cy + r >= GW - 1) ? 1e30f : (cy + r + 1) * CELLW - qy;
        const float dmin = fminf(fminf(sL, sR), fminf(sB, sT));
        done = done || (B * 1.00001f < dmin * dmin);
        if (__all_sync(0xffffffffu, done)) break;
    }

    // Butterfly merge across the 8 lanes of this group (exact lex order).
#pragma unroll
    for (int off = 1; off < QL; off <<= 1) {
        const u64 p0 = __shfl_xor_sync(0xffffffffu, k0, off);
        const u64 p1 = __shfl_xor_sync(0xffffffffu, k1, off);
        const u64 p2 = __shfl_xor_sync(0xffffffffu, k2, off);
        kins(p0, k0, k1, k2);
        kins(p1, k0, k1, k2);
        kins(p2, k0, k1, k2);
    }

    // Local -> global column index (low-word add; no carry possible since
    // idx < 4096 and base <= 12288), then exact merge of the 1.0 fillers.
    const u64 base = (u64)(c * NV);
    k0 += base; k1 += base; k2 += base;
    const unsigned fbase = (c == 0) ? NV : 0;
#pragma unroll
    for (int k = 0; k < 3; ++k)
        kins(((u64)0x3F800000u << 32) | (u64)(fbase + k), k0, k1, k2);

    const float d0 = key_d(k0), d1 = key_d(k1), d2 = key_d(k2);
    const int   g0 = key_i(k0), g1 = key_i(k1), g2 = key_i(k2);

    // softmax(-d), max-subtracted (d0 smallest).
    const float e1 = expf(d0 - d1);
    const float e2 = expf(d0 - d2);
    const float inv = 1.0f / (1.0f + e1 + e2);
    const float w0 = inv, w1 = e1 * inv, w2 = e2 * inv;

    // All 8 lanes hold the identical top-3; each writes one float4 chunk.
    const float4 a  = __ldg(&((const float4*)(feat + (size_t)g0 * DF))[lq]);
    const float4 b  = __ldg(&((const float4*)(feat + (size_t)g1 * DF))[lq]);
    const float4 cv = __ldg(&((const float4*)(feat + (size_t)g2 * DF))[lq]);
    float4 rr;
    rr.x = w0 * a.x + w1 * b.x + w2 * cv.x;
    rr.y = w0 * a.y + w1 * b.y + w2 * cv.y;
    rr.z = w0 * a.z + w1 * b.z + w2 * cv.z;
    rr.w = w0 * a.w + w1 * b.w + w2 * cv.w;
    ((float4*)(out + ((size_t)c * MV + m) * DF))[lq] = rr;
}

extern "C" void kernel_launch(void* const* d_in, const int* in_sizes, int n_in,
                              void* d_out, int out_size)
{
    const float* feat   = (const float*)d_in[0];  // (1, C*N, D)
    const float* verts  = (const float*)d_in[1];  // (C, N, 3)
    const float* nverts = (const float*)d_in[2];  // (C, M, 3)
    float* out = (float*)d_out;                   // (1, C*M, D)

    prep_kernel<<<2 * CC, 1024>>>(verts, nverts);

    const int smem = NV * sizeof(float4) + (NCELL + 1) * sizeof(int);
    cudaFuncSetAttribute(query_kernel,
                         cudaFuncAttributeMaxDynamicSharedMemorySize, smem);
    query_kernel<<<NBLK, TB, smem>>>(feat, nverts, out);
}